// round 8
// baseline (speedup 1.0000x reference)
#include <cuda_runtime.h>
#include <cuda_bf16.h>
#include <cstdint>

// LBP layer, fully fused, warp-strip, two s-columns per lane, predicated adds,
// float4 gray staging, 16 blocks/SM. Store guard fixed: lanes 0..29 store the
// block's 60 columns (lanes 30/31 only feed shuffles).
//   gray = dot(rgb, [0.2989, 0.587, 0.114])                (zero-padded outside)
//   s(y,x) = #{3x3 nbrs (incl. center): gray >= gray(y,x)} (s = 0 outside image)
//   lbp(y,x) = 1*s(y-1,x-1)+2*s(y-1,x)+4*s(y-1,x+1)
//            +128*s(y,x-1)           +8*s(y,x+1)
//            +64*s(y+1,x-1)+32*s(y+1,x)+16*s(y+1,x+1)
// Fixed shapes: N=32, H=W=512, C=3. Output [N,H,W,1] fp32.

#define OUT_PW   60                    // output columns per block (x0 % 4 == 0)
#define RPW      8                     // output rows per warp
#define NWARPS   4
#define TILE_H   (RPW * NWARPS)        // 32
#define G_COLS   68                    // gx0a = x0-4 .. x0+63 (covers halo+62)
#define G_STRIDE 68                    // 68*4B: rows 16B-aligned (272 = 17*16)
#define G_ROWS   (TILE_H + 4)          // 36
#define NTHREADS 128

__global__ __launch_bounds__(NTHREADS, 16) void lbp_warp2_kernel(
    const float* __restrict__ in,   // [N, H, W, 3]
    float* __restrict__ out,        // [N, H, W, 1]
    int H, int W)
{
    __shared__ __align__(16) float g[G_ROWS * G_STRIDE];   // 9.56 KB

    const int tid  = threadIdx.x;
    const int lane = tid & 31;
    const int wrp  = tid >> 5;
    const int bx = blockIdx.x, by = blockIdx.y, n = blockIdx.z;

    int x0 = bx * OUT_PW;
    if (x0 + OUT_PW > W) x0 = W - OUT_PW;     // 452 for last block: still %4==0
    const int gx0a = x0 - 4;                  // aligned gray tile origin (%4==0)
    const int gy0 = by * TILE_H - 2;

    const float* __restrict__ base = in + (size_t)n * H * W * 3;

    // ---------------- Phase 1: RGB -> gray into smem (zero outside image) ----
    const bool colsInterior = (gx0a >= 0) && (gx0a + G_COLS <= W);
    if (colsInterior) {
        // 3x LDG.128 -> 4 pixels. (gy*W+gx0a+4pc)*3 is a multiple of 4 floats.
        #pragma unroll 4
        for (int idx = tid; idx < G_ROWS * (G_COLS / 4); idx += NTHREADS) {
            const int r  = idx / (G_COLS / 4);
            const int pc = idx - r * (G_COLS / 4);
            const int gy = gy0 + r;
            float4 go = make_float4(0.f, 0.f, 0.f, 0.f);
            if ((unsigned)gy < (unsigned)H) {
                const int gx = gx0a + 4 * pc;
                const float4* p = (const float4*)(base + ((size_t)gy * W + gx) * 3);
                const float4 q0 = __ldg(p + 0);
                const float4 q1 = __ldg(p + 1);
                const float4 q2 = __ldg(p + 2);
                go.x = fmaf(0.2989f, q0.x, fmaf(0.587f, q0.y, 0.114f * q0.z));
                go.y = fmaf(0.2989f, q0.w, fmaf(0.587f, q1.x, 0.114f * q1.y));
                go.z = fmaf(0.2989f, q1.z, fmaf(0.587f, q1.w, 0.114f * q2.x));
                go.w = fmaf(0.2989f, q2.y, fmaf(0.587f, q2.z, 0.114f * q2.w));
            }
            *(float4*)&g[r * G_STRIDE + 4 * pc] = go;
        }
    } else {
        #pragma unroll 4
        for (int idx = tid; idx < G_ROWS * G_COLS; idx += NTHREADS) {
            const int r = idx / G_COLS;
            const int c = idx - r * G_COLS;
            const int gy = gy0 + r;
            const int gx = gx0a + c;
            float v = 0.0f;
            if ((unsigned)gy < (unsigned)H && (unsigned)gx < (unsigned)W) {
                const float* p = base + ((size_t)gy * W + gx) * 3;
                v = fmaf(0.2989f, __ldg(p), fmaf(0.587f, __ldg(p + 1), 0.114f * __ldg(p + 2)));
            }
            g[r * G_STRIDE + c] = v;
        }
    }
    __syncthreads();

    // ------------- Phase 2+3 fused: two rolling s-columns per lane -----------
    // Lane's s cols (global): csA = x0-1+2*lane, csB = csA+1.
    // Gray smem col for csA-1 = x0-2+2*lane = gx0a + (2 + 2*lane)  (even -> f2 ok)
    const int csA = x0 - 1 + 2 * lane;
    const bool colA = (unsigned)csA < (unsigned)W;
    const bool colB = (unsigned)(csA + 1) < (unsigned)W;
    const int r0 = by * TILE_H + wrp * RPW;

    const float* gp = &g[(wrp * RPW) * G_STRIDE + 2 + 2 * lane];

    float2 va = *(const float2*)(gp);     float2 va2 = *(const float2*)(gp + 2);
    float a0 = va.x, a1 = va.y, a2 = va2.x, a3 = va2.y;   gp += G_STRIDE;  // row r0-2
    float2 vb = *(const float2*)(gp);     float2 vb2 = *(const float2*)(gp + 2);
    float b0 = vb.x, b1 = vb.y, b2 = vb2.x, b3 = vb2.y;   gp += G_STRIDE;  // row r0-1

    float s2_0 = 0.f, s2_1 = 0.f, s2_2 = 0.f, s2_3 = 0.f;
    float s1_0 = 0.f, s1_1 = 0.f, s1_2 = 0.f, s1_3 = 0.f;

    const bool doStore = (lane <= 29);   // lanes 0..29 -> cols x0 .. x0+59
    float* op = out + (size_t)n * H * W + (size_t)r0 * W + (x0 + 2 * lane);

    #pragma unroll
    for (int i = 0; i < RPW + 2; i++) {
        const float2 vt  = *(const float2*)(gp);
        const float2 vt2 = *(const float2*)(gp + 2);
        const float t0 = vt.x, t1 = vt.y, t2 = vt2.x, t3 = vt2.y;
        gp += G_STRIDE;

        const int ys = r0 - 1 + i;
        const bool rowOk = (unsigned)ys < (unsigned)H;

        // two independent predicated-add chains (center b1 for A, b2 for B)
        float cA = 1.0f, cB = 1.0f;
        if (a0 >= b1) cA += 1.0f;
        if (a1 >= b2) cB += 1.0f;
        if (a1 >= b1) cA += 1.0f;
        if (a2 >= b2) cB += 1.0f;
        if (a2 >= b1) cA += 1.0f;
        if (a3 >= b2) cB += 1.0f;
        if (b0 >= b1) cA += 1.0f;
        if (b1 >= b2) cB += 1.0f;
        if (b2 >= b1) cA += 1.0f;
        if (b3 >= b2) cB += 1.0f;
        if (t0 >= b1) cA += 1.0f;
        if (t1 >= b2) cB += 1.0f;
        if (t1 >= b1) cA += 1.0f;
        if (t2 >= b2) cB += 1.0f;
        if (t2 >= b1) cA += 1.0f;
        if (t3 >= b2) cB += 1.0f;

        const float sa = (rowOk && colA) ? cA : 0.0f;   // zero-pad s
        const float sb = (rowOk && colB) ? cB : 0.0f;

        const float na = __shfl_down_sync(0xffffffffu, sa, 1);  // s col csA+2
        const float nb = __shfl_down_sync(0xffffffffu, sb, 1);  // s col csA+3

        if (i >= 2) {
            // emit row yo = ys-1, cols x0+2*lane and x0+2*lane+1
            float v0 = s2_0;
            v0 = fmaf(  2.0f, s2_1, v0);
            v0 = fmaf(  4.0f, s2_2, v0);
            v0 = fmaf(128.0f, s1_0, v0);
            v0 = fmaf(  8.0f, s1_2, v0);
            v0 = fmaf( 64.0f, sa,   v0);
            v0 = fmaf( 32.0f, sb,   v0);
            v0 = fmaf( 16.0f, na,   v0);

            float v1 = s2_1;
            v1 = fmaf(  2.0f, s2_2, v1);
            v1 = fmaf(  4.0f, s2_3, v1);
            v1 = fmaf(128.0f, s1_1, v1);
            v1 = fmaf(  8.0f, s1_3, v1);
            v1 = fmaf( 64.0f, sb,   v1);
            v1 = fmaf( 32.0f, na,   v1);
            v1 = fmaf( 16.0f, nb,   v1);

            if (doStore) *(float2*)op = make_float2(v0, v1);
            op += W;
        }

        s2_0 = s1_0; s2_1 = s1_1; s2_2 = s1_2; s2_3 = s1_3;
        s1_0 = sa;   s1_1 = sb;   s1_2 = na;   s1_3 = nb;
        a0 = b0; a1 = b1; a2 = b2; a3 = b3;
        b0 = t0; b1 = t1; b2 = t2; b3 = t3;
    }
}

extern "C" void kernel_launch(void* const* d_in, const int* in_sizes, int n_in,
                              void* d_out, int out_size)
{
    const float* in = (const float*)d_in[0];
    float* out = (float*)d_out;

    const int H = 512, W = 512;
    const int N = in_sizes[0] / (H * W * 3);

    dim3 grid((W + OUT_PW - 1) / OUT_PW, H / TILE_H, N);   // 9 x 16 x 32 = 4608
    lbp_warp2_kernel<<<grid, NTHREADS>>>(in, out, H, W);
}

// round 9
// speedup vs baseline: 1.1480x; 1.1480x over previous
#include <cuda_runtime.h>
#include <cuda_bf16.h>
#include <cstdint>

// LBP layer, fully fused, warp-strip, two s-columns per lane, predicated adds,
// float4 gray staging, block-uniform edge specialization (4 variants).
//   gray = dot(rgb, [0.2989, 0.587, 0.114])                (zero-padded outside)
//   s(y,x) = #{3x3 nbrs (incl. center): gray >= gray(y,x)} (s = 0 outside image)
//   lbp(y,x) = 1*s(y-1,x-1)+2*s(y-1,x)+4*s(y-1,x+1)
//            +128*s(y,x-1)           +8*s(y,x+1)
//            +64*s(y+1,x-1)+32*s(y+1,x)+16*s(y+1,x+1)
// Fixed shapes: N=32, H=W=512, C=3. Output [N,H,W,1] fp32.

#define OUT_PW   60                    // output columns per block (x0 % 4 == 0)
#define RPW      8                     // output rows per warp
#define NWARPS   4
#define TILE_H   (RPW * NWARPS)        // 32
#define G_COLS   68                    // gx0a = x0-4 .. x0+63
#define G_STRIDE 68                    // rows 16B-aligned (272B)
#define G_ROWS   (TILE_H + 4)          // 36
#define NTHREADS 128
#define GX 9
#define GY 16

// Fused neighbor-count + LBP stencil, rolling registers, shuffle exchange.
// XE: block touches left/right image edge (needs column guards).
// YE: block touches top/bottom image edge (needs row guards).
template<bool XE, bool YE>
__device__ __forceinline__ void lbp_phase23(
    const float* __restrict__ g, float* __restrict__ outn,
    int x0, int by, int wrp, int lane, int H, int W)
{
    const int csA = x0 - 1 + 2 * lane;
    const bool colA = XE ? ((unsigned)csA < (unsigned)W) : true;
    const bool colB = XE ? ((unsigned)(csA + 1) < (unsigned)W) : true;
    const int r0 = by * TILE_H + wrp * RPW;

    const float* gp = &g[(wrp * RPW) * G_STRIDE + 2 + 2 * lane];

    float2 va = *(const float2*)(gp);     float2 va2 = *(const float2*)(gp + 2);
    float a0 = va.x, a1 = va.y, a2 = va2.x, a3 = va2.y;   gp += G_STRIDE;
    float2 vb = *(const float2*)(gp);     float2 vb2 = *(const float2*)(gp + 2);
    float b0 = vb.x, b1 = vb.y, b2 = vb2.x, b3 = vb2.y;   gp += G_STRIDE;

    float s2_0 = 0.f, s2_1 = 0.f, s2_2 = 0.f, s2_3 = 0.f;
    float s1_0 = 0.f, s1_1 = 0.f, s1_2 = 0.f, s1_3 = 0.f;

    const bool doStore = (lane <= 29);   // lanes 0..29 -> cols x0 .. x0+59
    float* op = outn + (size_t)r0 * W + (x0 + 2 * lane);

    #pragma unroll
    for (int i = 0; i < RPW + 2; i++) {
        const float2 vt  = *(const float2*)(gp);
        const float2 vt2 = *(const float2*)(gp + 2);
        const float t0 = vt.x, t1 = vt.y, t2 = vt2.x, t3 = vt2.y;
        gp += G_STRIDE;

        // two independent compare-accumulate chains (centers b1, b2)
        float cA = 1.0f, cB = 1.0f;
        cA += (a0 >= b1) ? 1.0f : 0.0f;
        cB += (a1 >= b2) ? 1.0f : 0.0f;
        cA += (a1 >= b1) ? 1.0f : 0.0f;
        cB += (a2 >= b2) ? 1.0f : 0.0f;
        cA += (a2 >= b1) ? 1.0f : 0.0f;
        cB += (a3 >= b2) ? 1.0f : 0.0f;
        cA += (b0 >= b1) ? 1.0f : 0.0f;
        cB += (b1 >= b2) ? 1.0f : 0.0f;
        cA += (b2 >= b1) ? 1.0f : 0.0f;
        cB += (b3 >= b2) ? 1.0f : 0.0f;
        cA += (t0 >= b1) ? 1.0f : 0.0f;
        cB += (t1 >= b2) ? 1.0f : 0.0f;
        cA += (t1 >= b1) ? 1.0f : 0.0f;
        cB += (t2 >= b2) ? 1.0f : 0.0f;
        cA += (t2 >= b1) ? 1.0f : 0.0f;
        cB += (t3 >= b2) ? 1.0f : 0.0f;

        float sa, sb;
        if (YE) {
            const int ys = r0 - 1 + i;
            const bool rowOk = (unsigned)ys < (unsigned)H;
            sa = (rowOk && colA) ? cA : 0.0f;     // zero-pad s
            sb = (rowOk && colB) ? cB : 0.0f;
        } else if (XE) {
            sa = colA ? cA : 0.0f;
            sb = colB ? cB : 0.0f;
        } else {
            sa = cA;                              // interior: no guards at all
            sb = cB;
        }

        const float na = __shfl_down_sync(0xffffffffu, sa, 1);  // s col csA+2
        const float nb = __shfl_down_sync(0xffffffffu, sb, 1);  // s col csA+3

        if (i >= 2) {
            float v0 = s2_0;
            v0 = fmaf(  2.0f, s2_1, v0);
            v0 = fmaf(  4.0f, s2_2, v0);
            v0 = fmaf(128.0f, s1_0, v0);
            v0 = fmaf(  8.0f, s1_2, v0);
            v0 = fmaf( 64.0f, sa,   v0);
            v0 = fmaf( 32.0f, sb,   v0);
            v0 = fmaf( 16.0f, na,   v0);

            float v1 = s2_1;
            v1 = fmaf(  2.0f, s2_2, v1);
            v1 = fmaf(  4.0f, s2_3, v1);
            v1 = fmaf(128.0f, s1_1, v1);
            v1 = fmaf(  8.0f, s1_3, v1);
            v1 = fmaf( 64.0f, sb,   v1);
            v1 = fmaf( 32.0f, na,   v1);
            v1 = fmaf( 16.0f, nb,   v1);

            if (doStore) *(float2*)op = make_float2(v0, v1);
            op += W;
        }

        s2_0 = s1_0; s2_1 = s1_1; s2_2 = s1_2; s2_3 = s1_3;
        s1_0 = sa;   s1_1 = sb;   s1_2 = na;   s1_3 = nb;
        a0 = b0; a1 = b1; a2 = b2; a3 = b3;
        b0 = t0; b1 = t1; b2 = t2; b3 = t3;
    }
}

__global__ __launch_bounds__(NTHREADS, 12) void lbp_warp2_kernel(
    const float* __restrict__ in,   // [N, H, W, 3]
    float* __restrict__ out,        // [N, H, W, 1]
    int H, int W)
{
    __shared__ __align__(16) float g[G_ROWS * G_STRIDE];   // 9.56 KB

    const int tid  = threadIdx.x;
    const int lane = tid & 31;
    const int wrp  = tid >> 5;
    const int bx = blockIdx.x, by = blockIdx.y, n = blockIdx.z;

    const bool xe = (bx == 0) || (bx == GX - 1);
    const bool ye = (by == 0) || (by == GY - 1);

    int x0 = bx * OUT_PW;
    if (x0 + OUT_PW > W) x0 = W - OUT_PW;     // 452 for last block (%4==0)
    const int gx0a = x0 - 4;
    const int gy0 = by * TILE_H - 2;

    const float* __restrict__ base = in + (size_t)n * H * W * 3;

    // ---------------- Phase 1: RGB -> gray into smem ----------------
    if (!xe) {
        if (!ye) {
            // fully interior: no guards, 3x LDG.128 per 4 pixels
            #pragma unroll 4
            for (int idx = tid; idx < G_ROWS * (G_COLS / 4); idx += NTHREADS) {
                const int r  = idx / (G_COLS / 4);
                const int pc = idx - r * (G_COLS / 4);
                const int gy = gy0 + r;
                const int gx = gx0a + 4 * pc;
                const float4* p = (const float4*)(base + ((size_t)gy * W + gx) * 3);
                const float4 q0 = __ldg(p + 0);
                const float4 q1 = __ldg(p + 1);
                const float4 q2 = __ldg(p + 2);
                float4 go;
                go.x = fmaf(0.2989f, q0.x, fmaf(0.587f, q0.y, 0.114f * q0.z));
                go.y = fmaf(0.2989f, q0.w, fmaf(0.587f, q1.x, 0.114f * q1.y));
                go.z = fmaf(0.2989f, q1.z, fmaf(0.587f, q1.w, 0.114f * q2.x));
                go.w = fmaf(0.2989f, q2.y, fmaf(0.587f, q2.z, 0.114f * q2.w));
                *(float4*)&g[r * G_STRIDE + 4 * pc] = go;
            }
        } else {
            // y-edge: row guard only
            #pragma unroll 4
            for (int idx = tid; idx < G_ROWS * (G_COLS / 4); idx += NTHREADS) {
                const int r  = idx / (G_COLS / 4);
                const int pc = idx - r * (G_COLS / 4);
                const int gy = gy0 + r;
                float4 go = make_float4(0.f, 0.f, 0.f, 0.f);
                if ((unsigned)gy < (unsigned)H) {
                    const int gx = gx0a + 4 * pc;
                    const float4* p = (const float4*)(base + ((size_t)gy * W + gx) * 3);
                    const float4 q0 = __ldg(p + 0);
                    const float4 q1 = __ldg(p + 1);
                    const float4 q2 = __ldg(p + 2);
                    go.x = fmaf(0.2989f, q0.x, fmaf(0.587f, q0.y, 0.114f * q0.z));
                    go.y = fmaf(0.2989f, q0.w, fmaf(0.587f, q1.x, 0.114f * q1.y));
                    go.z = fmaf(0.2989f, q1.z, fmaf(0.587f, q1.w, 0.114f * q2.x));
                    go.w = fmaf(0.2989f, q2.y, fmaf(0.587f, q2.z, 0.114f * q2.w));
                }
                *(float4*)&g[r * G_STRIDE + 4 * pc] = go;
            }
        }
    } else {
        // x-edge: scalar fully-guarded path
        #pragma unroll 4
        for (int idx = tid; idx < G_ROWS * G_COLS; idx += NTHREADS) {
            const int r = idx / G_COLS;
            const int c = idx - r * G_COLS;
            const int gy = gy0 + r;
            const int gx = gx0a + c;
            float v = 0.0f;
            if ((unsigned)gy < (unsigned)H && (unsigned)gx < (unsigned)W) {
                const float* p = base + ((size_t)gy * W + gx) * 3;
                v = fmaf(0.2989f, __ldg(p), fmaf(0.587f, __ldg(p + 1), 0.114f * __ldg(p + 2)));
            }
            g[r * G_STRIDE + c] = v;
        }
    }
    __syncthreads();

    // ------------- Phase 2+3 fused: specialized per block class -------------
    float* outn = out + (size_t)n * H * W;
    if (!xe && !ye)      lbp_phase23<false, false>(g, outn, x0, by, wrp, lane, H, W);
    else if (!xe)        lbp_phase23<false, true >(g, outn, x0, by, wrp, lane, H, W);
    else if (!ye)        lbp_phase23<true,  false>(g, outn, x0, by, wrp, lane, H, W);
    else                 lbp_phase23<true,  true >(g, outn, x0, by, wrp, lane, H, W);
}

extern "C" void kernel_launch(void* const* d_in, const int* in_sizes, int n_in,
                              void* d_out, int out_size)
{
    const float* in = (const float*)d_in[0];
    float* out = (float*)d_out;

    const int H = 512, W = 512;
    const int N = in_sizes[0] / (H * W * 3);

    dim3 grid(GX, GY, N);   // 9 x 16 x 32 = 4608
    lbp_warp2_kernel<<<grid, NTHREADS>>>(in, out, H, W);
}

// round 10
// speedup vs baseline: 1.1584x; 1.0090x over previous
#include <cuda_runtime.h>
#include <cuda_bf16.h>
#include <cstdint>

// LBP layer, fully fused, warp-strip, two s-columns per lane, edge-specialized,
// packed f32x2 LBP accumulation (Blackwell fma.rn.f32x2).
//   gray = dot(rgb, [0.2989, 0.587, 0.114])                (zero-padded outside)
//   s(y,x) = #{3x3 nbrs (incl. center): gray >= gray(y,x)} (s = 0 outside image)
//   lbp(y,x) = 1*s(y-1,x-1)+2*s(y-1,x)+4*s(y-1,x+1)
//            +128*s(y,x-1)           +8*s(y,x+1)
//            +64*s(y+1,x-1)+32*s(y+1,x)+16*s(y+1,x+1)
// Fixed shapes: N=32, H=W=512, C=3. Output [N,H,W,1] fp32.

#define OUT_PW   60
#define RPW      8
#define NWARPS   4
#define TILE_H   (RPW * NWARPS)        // 32
#define G_COLS   68
#define G_STRIDE 68
#define G_ROWS   (TILE_H + 4)          // 36
#define NTHREADS 128
#define GX 9
#define GY 16

typedef unsigned long long ull;

// packed-f32x2 helpers
__device__ __forceinline__ ull pk2(float lo, float hi) {
    ull r;
    asm("mov.b64 %0, {%1, %2};" : "=l"(r) : "f"(lo), "f"(hi));
    return r;
}
__device__ __forceinline__ ull ffma2(ull a, ull b, ull c) {
    ull d;
    asm("fma.rn.f32x2 %0, %1, %2, %3;" : "=l"(d) : "l"(a), "l"(b), "l"(c));
    return d;
}
__device__ __forceinline__ ull fmul2(ull a, ull b) {
    ull d;
    asm("mul.rn.f32x2 %0, %1, %2;" : "=l"(d) : "l"(a), "l"(b));
    return d;
}

// weight constants, same fp32 value in both halves
#define WPK(bits) ((((ull)(bits)) << 32) | (ull)(bits))
__device__ const ull W2q   = WPK(0x40000000u);   // (2,2)
__device__ const ull W4q   = WPK(0x40800000u);   // (4,4)
__device__ const ull W8q   = WPK(0x41000000u);   // (8,8)
__device__ const ull W16q  = WPK(0x41800000u);   // (16,16)
__device__ const ull W32q  = WPK(0x42000000u);   // (32,32)
__device__ const ull W64q  = WPK(0x42800000u);   // (64,64)
__device__ const ull W128q = WPK(0x43000000u);   // (128,128)

// Fused neighbor-count + LBP stencil, rolling packed registers, shuffle exchange.
template<bool XE, bool YE>
__device__ __forceinline__ void lbp_phase23(
    const float* __restrict__ g, float* __restrict__ outn,
    int x0, int by, int wrp, int lane, int H, int W)
{
    const int csA = x0 - 1 + 2 * lane;
    const bool colA = XE ? ((unsigned)csA < (unsigned)W) : true;
    const bool colB = XE ? ((unsigned)(csA + 1) < (unsigned)W) : true;
    const int r0 = by * TILE_H + wrp * RPW;

    const float* gp = &g[(wrp * RPW) * G_STRIDE + 2 + 2 * lane];

    float2 va = *(const float2*)(gp);     float2 va2 = *(const float2*)(gp + 2);
    float a0 = va.x, a1 = va.y, a2 = va2.x, a3 = va2.y;   gp += G_STRIDE;
    float2 vb = *(const float2*)(gp);     float2 vb2 = *(const float2*)(gp + 2);
    float b0 = vb.x, b1 = vb.y, b2 = vb2.x, b3 = vb2.y;   gp += G_STRIDE;

    // packed s-pair rolling state: P1=(sa,sb) P2=(sb,na) P3=(na,nb)
    // Q* = two iters ago (weights 1/2/4), R* = one iter ago (128/-/8)
    ull Q1 = 0, Q2 = 0, Q3 = 0;
    ull R1 = 0, R2 = 0, R3 = 0;

    const bool doStore = (lane <= 29);   // lanes 0..29 -> cols x0 .. x0+59
    float* op = outn + (size_t)r0 * W + (x0 + 2 * lane);

    #pragma unroll
    for (int i = 0; i < RPW + 2; i++) {
        const float2 vt  = *(const float2*)(gp);
        const float2 vt2 = *(const float2*)(gp + 2);
        const float t0 = vt.x, t1 = vt.y, t2 = vt2.x, t3 = vt2.y;
        gp += G_STRIDE;

        // two independent compare-accumulate chains (centers b1, b2)
        float cA = 1.0f, cB = 1.0f;
        cA += (a0 >= b1) ? 1.0f : 0.0f;
        cB += (a1 >= b2) ? 1.0f : 0.0f;
        cA += (a1 >= b1) ? 1.0f : 0.0f;
        cB += (a2 >= b2) ? 1.0f : 0.0f;
        cA += (a2 >= b1) ? 1.0f : 0.0f;
        cB += (a3 >= b2) ? 1.0f : 0.0f;
        cA += (b0 >= b1) ? 1.0f : 0.0f;
        cB += (b1 >= b2) ? 1.0f : 0.0f;
        cA += (b2 >= b1) ? 1.0f : 0.0f;
        cB += (b3 >= b2) ? 1.0f : 0.0f;
        cA += (t0 >= b1) ? 1.0f : 0.0f;
        cB += (t1 >= b2) ? 1.0f : 0.0f;
        cA += (t1 >= b1) ? 1.0f : 0.0f;
        cB += (t2 >= b2) ? 1.0f : 0.0f;
        cA += (t2 >= b1) ? 1.0f : 0.0f;
        cB += (t3 >= b2) ? 1.0f : 0.0f;

        float sa, sb;
        if (YE) {
            const int ys = r0 - 1 + i;
            const bool rowOk = (unsigned)ys < (unsigned)H;
            sa = (rowOk && colA) ? cA : 0.0f;     // zero-pad s
            sb = (rowOk && colB) ? cB : 0.0f;
        } else if (XE) {
            sa = colA ? cA : 0.0f;
            sb = colB ? cB : 0.0f;
        } else {
            sa = cA;
            sb = cB;
        }

        const float na = __shfl_down_sync(0xffffffffu, sa, 1);  // s col csA+2
        const float nb = __shfl_down_sync(0xffffffffu, sb, 1);  // s col csA+3

        const ull P1 = pk2(sa, sb);
        const ull P2 = pk2(sb, na);
        const ull P3 = pk2(na, nb);

        if (i >= 2) {
            // (v0,v1) = 1*Q1 + 2*Q2 + 4*Q3 + 128*R1 + 8*R3 + 64*P1 + 32*P2 + 16*P3
            ull vA = Q1;
            vA = ffma2(Q2, W2q,   vA);
            vA = ffma2(Q3, W4q,   vA);
            vA = ffma2(R1, W128q, vA);
            ull vB = fmul2(R3, W8q);
            vB = ffma2(P1, W64q, vB);
            vB = ffma2(P2, W32q, vB);
            vB = ffma2(P3, W16q, vB);
            ull v;
            asm("add.rn.f32x2 %0, %1, %2;" : "=l"(v) : "l"(vA), "l"(vB));
            if (doStore) *(ull*)op = v;            // two fp32 outputs, 8B aligned
            op += W;
        }

        Q1 = R1; Q2 = R2; Q3 = R3;
        R1 = P1; R2 = P2; R3 = P3;
        a0 = b0; a1 = b1; a2 = b2; a3 = b3;
        b0 = t0; b1 = t1; b2 = t2; b3 = t3;
    }
}

__global__ __launch_bounds__(NTHREADS, 10) void lbp_warp2_kernel(
    const float* __restrict__ in,   // [N, H, W, 3]
    float* __restrict__ out,        // [N, H, W, 1]
    int H, int W)
{
    __shared__ __align__(16) float g[G_ROWS * G_STRIDE];   // 9.56 KB

    const int tid  = threadIdx.x;
    const int lane = tid & 31;
    const int wrp  = tid >> 5;
    const int bx = blockIdx.x, by = blockIdx.y, n = blockIdx.z;

    const bool xe = (bx == 0) || (bx == GX - 1);
    const bool ye = (by == 0) || (by == GY - 1);

    int x0 = bx * OUT_PW;
    if (x0 + OUT_PW > W) x0 = W - OUT_PW;     // 452 for last block (%4==0)
    const int gx0a = x0 - 4;
    const int gy0 = by * TILE_H - 2;

    const float* __restrict__ base = in + (size_t)n * H * W * 3;

    // ---------------- Phase 1: RGB -> gray into smem ----------------
    if (!xe) {
        if (!ye) {
            #pragma unroll 4
            for (int idx = tid; idx < G_ROWS * (G_COLS / 4); idx += NTHREADS) {
                const int r  = idx / (G_COLS / 4);
                const int pc = idx - r * (G_COLS / 4);
                const int gy = gy0 + r;
                const int gx = gx0a + 4 * pc;
                const float4* p = (const float4*)(base + ((size_t)gy * W + gx) * 3);
                const float4 q0 = __ldg(p + 0);
                const float4 q1 = __ldg(p + 1);
                const float4 q2 = __ldg(p + 2);
                float4 go;
                go.x = fmaf(0.2989f, q0.x, fmaf(0.587f, q0.y, 0.114f * q0.z));
                go.y = fmaf(0.2989f, q0.w, fmaf(0.587f, q1.x, 0.114f * q1.y));
                go.z = fmaf(0.2989f, q1.z, fmaf(0.587f, q1.w, 0.114f * q2.x));
                go.w = fmaf(0.2989f, q2.y, fmaf(0.587f, q2.z, 0.114f * q2.w));
                *(float4*)&g[r * G_STRIDE + 4 * pc] = go;
            }
        } else {
            #pragma unroll 4
            for (int idx = tid; idx < G_ROWS * (G_COLS / 4); idx += NTHREADS) {
                const int r  = idx / (G_COLS / 4);
                const int pc = idx - r * (G_COLS / 4);
                const int gy = gy0 + r;
                float4 go = make_float4(0.f, 0.f, 0.f, 0.f);
                if ((unsigned)gy < (unsigned)H) {
                    const int gx = gx0a + 4 * pc;
                    const float4* p = (const float4*)(base + ((size_t)gy * W + gx) * 3);
                    const float4 q0 = __ldg(p + 0);
                    const float4 q1 = __ldg(p + 1);
                    const float4 q2 = __ldg(p + 2);
                    go.x = fmaf(0.2989f, q0.x, fmaf(0.587f, q0.y, 0.114f * q0.z));
                    go.y = fmaf(0.2989f, q0.w, fmaf(0.587f, q1.x, 0.114f * q1.y));
                    go.z = fmaf(0.2989f, q1.z, fmaf(0.587f, q1.w, 0.114f * q2.x));
                    go.w = fmaf(0.2989f, q2.y, fmaf(0.587f, q2.z, 0.114f * q2.w));
                }
                *(float4*)&g[r * G_STRIDE + 4 * pc] = go;
            }
        }
    } else {
        #pragma unroll 4
        for (int idx = tid; idx < G_ROWS * G_COLS; idx += NTHREADS) {
            const int r = idx / G_COLS;
            const int c = idx - r * G_COLS;
            const int gy = gy0 + r;
            const int gx = gx0a + c;
            float v = 0.0f;
            if ((unsigned)gy < (unsigned)H && (unsigned)gx < (unsigned)W) {
                const float* p = base + ((size_t)gy * W + gx) * 3;
                v = fmaf(0.2989f, __ldg(p), fmaf(0.587f, __ldg(p + 1), 0.114f * __ldg(p + 2)));
            }
            g[r * G_STRIDE + c] = v;
        }
    }
    __syncthreads();

    // ------------- Phase 2+3 fused: specialized per block class -------------
    float* outn = out + (size_t)n * H * W;
    if (!xe && !ye)      lbp_phase23<false, false>(g, outn, x0, by, wrp, lane, H, W);
    else if (!xe)        lbp_phase23<false, true >(g, outn, x0, by, wrp, lane, H, W);
    else if (!ye)        lbp_phase23<true,  false>(g, outn, x0, by, wrp, lane, H, W);
    else                 lbp_phase23<true,  true >(g, outn, x0, by, wrp, lane, H, W);
}

extern "C" void kernel_launch(void* const* d_in, const int* in_sizes, int n_in,
                              void* d_out, int out_size)
{
    const float* in = (const float*)d_in[0];
    float* out = (float*)d_out;

    const int H = 512, W = 512;
    const int N = in_sizes[0] / (H * W * 3);

    dim3 grid(GX, GY, N);   // 9 x 16 x 32 = 4608
    lbp_warp2_kernel<<<grid, NTHREADS>>>(in, out, H, W);
}